// round 14
// baseline (speedup 1.0000x reference)
#include <cuda_runtime.h>

// Problem constants
#define YY 5
#define NN 200000
#define GG 128
#define II 128
#define RR 3
#define BB 1024
#define KK 64
#define KTOT (RR * GG)   // 384

#define NWEFF_BLK 192    // weff-builder CTAs prepended to gather grid
#define NSPLIT 4         // GEMM K-split factor
#define MTOT (YY * BB)   // 5120

// Scratch (no cudaMalloc allowed)
__device__ __align__(16) float g_mean[(size_t)MTOT * KTOT];        // [m][k]
__device__ __align__(16) float g_weff[KTOT * II];                  // [k][i]
__device__ __align__(16) float g_part[NSPLIT][(size_t)MTOT * II];  // partials
__device__ int g_ycnt[YY];   // gather CTAs completed per year (0-init; reset by reduce)
__device__ int g_wdone;      // weff blocks completed

__device__ __forceinline__ void pdl_trigger() {
    asm volatile("griddepcontrol.launch_dependents;");
}

// ---------------------------------------------------------------------------
// Fused kernel #1 (1D grid, 128 threads)  — EXACT R8 gather (41.1us measured)
// plus per-year completion counters for PDL overlap:
//   blocks [0, 192):         build g_weff  -> g_wdone
//   blocks [192, 192+15360): gather + masked mean (CTA per (y,r,b)) -> g_ycnt[y]
// ---------------------------------------------------------------------------
__global__ void __launch_bounds__(128) gather_mean_kernel(
        const float* __restrict__ emb,
        const void* __restrict__ nbr,
        const void* __restrict__ cnt,
        const float* __restrict__ Wrel,
        const float* __restrict__ Wcite) {
    const int bid = blockIdx.x;
    const int tid = threadIdx.x;

    if (bid < NWEFF_BLK) {
        #pragma unroll
        for (int j = 0; j < 2; ++j) {
            int idx = bid * 256 + j * 128 + tid;   // < 49152
            int r  = idx / (GG * II);
            int gi = idx - r * (GG * II);
            float v;
            if (r == 0)
                v = Wcite[gi] + Wcite[GG * II + gi] + Wcite[2 * GG * II + gi];
            else
                v = Wrel[idx];
            g_weff[idx] = v;
        }
        __threadfence();
        if (tid == 0) atomicAdd(&g_wdone, 1);
        pdl_trigger();
        return;
    }

    const int gid = bid - NWEFF_BLK;
    const int y   = gid / (RR * BB);
    const int rem = gid - y * (RR * BB);
    const int r   = rem >> 10;
    const int b   = rem & (BB - 1);
    const int w    = tid >> 5;
    const int lane = tid & 31;

    __shared__ int   s_is64;
    __shared__ int   s_cnt;
    __shared__ __align__(16) int   sidx[KK];
    __shared__ __align__(16) float part[4][GG];

    // dtype detection (warp 0): odd words of first 32 int64 candidates
    if (w == 0) {
        unsigned int v = ((const unsigned int*)cnt)[2 * lane + 1];
        unsigned int m = __ballot_sync(0xffffffffu, v != 0u);
        if (lane == 0) s_is64 = (m == 0u) ? 1 : 0;
    }
    __syncthreads();
    const int is64 = s_is64;

    const long long lin = ((long long)y * RR + r) * BB + b;
    if (tid == 0) {
        s_cnt = is64 ? (int)((const long long*)cnt)[lin]
                     : ((const int*)cnt)[lin];
    }
    if (tid < KK) {
        sidx[tid] = is64 ? (int)((const long long*)nbr)[lin * KK + tid]
                         : ((const int*)nbr)[lin * KK + tid];
    }
    __syncthreads();
    const int count = s_cnt;

    // float4 view of this year's embedding slab; row stride = 32 float4s
    const float4* e = (const float4*)(emb + (size_t)y * NN * GG) + lane;

    float4 acc = make_float4(0.f, 0.f, 0.f, 0.f);
    int k = w;
    for (; k + 4 < count; k += 8) {
        float4 v0 = e[(size_t)sidx[k] * 32];
        float4 v1 = e[(size_t)sidx[k + 4] * 32];
        acc.x += v0.x + v1.x;
        acc.y += v0.y + v1.y;
        acc.z += v0.z + v1.z;
        acc.w += v0.w + v1.w;
    }
    if (k < count) {
        float4 v0 = e[(size_t)sidx[k] * 32];
        acc.x += v0.x; acc.y += v0.y; acc.z += v0.z; acc.w += v0.w;
    }

    *(float4*)&part[w][lane * 4] = acc;
    __syncthreads();

    const float inv = 1.0f / (float)(count > 0 ? count : 1);
    float s = part[0][tid] + part[1][tid] + part[2][tid] + part[3][tid];
    g_mean[((size_t)y * BB + b) * KTOT + r * GG + tid] = s * inv;

    __threadfence();
    __syncthreads();
    if (tid == 0) atomicAdd(&g_ycnt[y], 1);
    pdl_trigger();
}

// ---------------------------------------------------------------------------
// K-split SGEMM partials (EXACT R8 shape) with PDL spin preamble:
// waits until all gather CTAs of its year (and weff) are done, so this kernel
// can start executing while the gather kernel is still running (PDL).
// Tile BM=32 x BN=128, BK=32, 3 chunks; 128 threads; grid = 160 x 4 = 640.
// ---------------------------------------------------------------------------
#define BM 32
#define BN 128
#define BK 32
#define KSPL (KTOT / NSPLIT)    // 96
#define NCHUNK (KSPL / BK)      // 3
#define APAD 8

__device__ __forceinline__ unsigned long long fma2(unsigned long long a,
                                                   unsigned long long b,
                                                   unsigned long long c) {
    unsigned long long d;
    asm("fma.rn.f32x2 %0, %1, %2, %3;" : "=l"(d) : "l"(a), "l"(b), "l"(c));
    return d;
}
__device__ __forceinline__ unsigned long long dup2(float x) {
    unsigned long long d;
    unsigned int u = __float_as_uint(x);
    asm("mov.b64 %0, {%1, %1};" : "=l"(d) : "r"(u));
    return d;
}
__device__ __forceinline__ float2 unpk2(unsigned long long p) {
    unsigned int lo, hi;
    asm("mov.b64 {%0, %1}, %2;" : "=r"(lo), "=r"(hi) : "l"(p));
    return make_float2(__uint_as_float(lo), __uint_as_float(hi));
}
__device__ __forceinline__ void cp_async16(unsigned int smem_addr,
                                           const void* gptr) {
    asm volatile("cp.async.ca.shared.global [%0], [%1], 16;\n"
                 :: "r"(smem_addr), "l"(gptr));
}
__device__ __forceinline__ void cp_async_commit() {
    asm volatile("cp.async.commit_group;\n");
}
__device__ __forceinline__ void cp_async_wait0() {
    asm volatile("cp.async.wait_group 0;\n");
}

__global__ void __launch_bounds__(128) gemm_partial_kernel() {
    __shared__ __align__(16) float Ast[2][BK][BM + APAD];  // transposed A
    __shared__ __align__(16) float Ws[2][BK][BN];

    const int tid  = threadIdx.x;        // 0..127
    const int w    = tid >> 5;           // warp 0..3 -> rows w*8..w*8+7
    const int lane = tid & 31;           // cols lane*4..lane*4+3
    const int ksplit  = blockIdx.x & (NSPLIT - 1);
    const int rowbase = (blockIdx.x >> 2) * BM;
    const int kbase   = ksplit * KSPL;
    const int yy      = rowbase >> 10;   // year of this row tile

    // spin until this year's gather inputs (and Weff) are complete
    if (tid == 0) {
        volatile int* wd = &g_wdone;
        volatile int* yc = &g_ycnt[yy];
        while (*wd < NWEFF_BLK || *yc < RR * BB) __nanosleep(128);
    }
    __syncthreads();
    __threadfence();   // acquire: producer writes visible

    unsigned long long acc[4][4];        // [rowpair][col]
    #pragma unroll
    for (int i = 0; i < 4; ++i)
        #pragma unroll
        for (int j = 0; j < 4; ++j) acc[i][j] = 0ull;

    const float* Ag = g_mean + (size_t)rowbase * KTOT + kbase;
    const float* Wg = g_weff + (size_t)kbase * BN;

    const int wrow = tid >> 5;           // 0..3   (k within chunk, +4 per j)
    const int wcol = (tid & 31) << 2;    // 0..124

    unsigned int ws_base[2];
    ws_base[0] = (unsigned int)__cvta_generic_to_shared(&Ws[0][0][0]);
    ws_base[1] = (unsigned int)__cvta_generic_to_shared(&Ws[1][0][0]);

    // prologue: stage chunk 0 (A: 2 float4/thread; W: 8 cp.async/thread)
    {
        #pragma unroll
        for (int j = 0; j < 2; ++j) {
            int l = tid + j * 128;
            int rr = l >> 3, kc = (l & 7) << 2;
            float4 pa = *(const float4*)(Ag + (size_t)rr * KTOT + kc);
            Ast[0][kc + 0][rr] = pa.x;
            Ast[0][kc + 1][rr] = pa.y;
            Ast[0][kc + 2][rr] = pa.z;
            Ast[0][kc + 3][rr] = pa.w;
        }
        #pragma unroll
        for (int j = 0; j < 8; ++j) {
            int kr = wrow + j * 4;       // 0..31
            cp_async16(ws_base[0] + (unsigned int)((kr * BN + wcol) * 4),
                       Wg + (size_t)kr * BN + wcol);
        }
        cp_async_commit();
        cp_async_wait0();
    }
    __syncthreads();

    for (int c = 0; c < NCHUNK; ++c) {
        const int buf = c & 1;
        const bool more = (c + 1 < NCHUNK);
        float4 pa0, pa1;
        if (more) {
            const int k0 = (c + 1) * BK;
            {
                int l = tid;
                pa0 = *(const float4*)(Ag + (size_t)(l >> 3) * KTOT + k0 + ((l & 7) << 2));
                l = tid + 128;
                pa1 = *(const float4*)(Ag + (size_t)(l >> 3) * KTOT + k0 + ((l & 7) << 2));
            }
            #pragma unroll
            for (int j = 0; j < 8; ++j) {
                int kr = wrow + j * 4;
                cp_async16(ws_base[buf ^ 1] + (unsigned int)((kr * BN + wcol) * 4),
                           Wg + (size_t)(k0 + kr) * BN + wcol);
            }
            cp_async_commit();
        }

        #pragma unroll
        for (int kk = 0; kk < BK; ++kk) {
            ulonglong2 aP0 = *(const ulonglong2*)&Ast[buf][kk][w * 8];      // rows 0-3
            ulonglong2 aP1 = *(const ulonglong2*)&Ast[buf][kk][w * 8 + 4];  // rows 4-7
            float4 w4 = *(const float4*)&Ws[buf][kk][lane * 4];
            unsigned long long wd0 = dup2(w4.x), wd1 = dup2(w4.y);
            unsigned long long wd2 = dup2(w4.z), wd3 = dup2(w4.w);

            acc[0][0] = fma2(aP0.x, wd0, acc[0][0]);
            acc[0][1] = fma2(aP0.x, wd1, acc[0][1]);
            acc[0][2] = fma2(aP0.x, wd2, acc[0][2]);
            acc[0][3] = fma2(aP0.x, wd3, acc[0][3]);
            acc[1][0] = fma2(aP0.y, wd0, acc[1][0]);
            acc[1][1] = fma2(aP0.y, wd1, acc[1][1]);
            acc[1][2] = fma2(aP0.y, wd2, acc[1][2]);
            acc[1][3] = fma2(aP0.y, wd3, acc[1][3]);
            acc[2][0] = fma2(aP1.x, wd0, acc[2][0]);
            acc[2][1] = fma2(aP1.x, wd1, acc[2][1]);
            acc[2][2] = fma2(aP1.x, wd2, acc[2][2]);
            acc[2][3] = fma2(aP1.x, wd3, acc[2][3]);
            acc[3][0] = fma2(aP1.y, wd0, acc[3][0]);
            acc[3][1] = fma2(aP1.y, wd1, acc[3][1]);
            acc[3][2] = fma2(aP1.y, wd2, acc[3][2]);
            acc[3][3] = fma2(aP1.y, wd3, acc[3][3]);
        }

        if (more) {
            const int nbuf = buf ^ 1;
            {
                int l = tid;
                int rr = l >> 3, kc = (l & 7) << 2;
                Ast[nbuf][kc + 0][rr] = pa0.x;
                Ast[nbuf][kc + 1][rr] = pa0.y;
                Ast[nbuf][kc + 2][rr] = pa0.z;
                Ast[nbuf][kc + 3][rr] = pa0.w;
                l = tid + 128;
                rr = l >> 3; kc = (l & 7) << 2;
                Ast[nbuf][kc + 0][rr] = pa1.x;
                Ast[nbuf][kc + 1][rr] = pa1.y;
                Ast[nbuf][kc + 2][rr] = pa1.z;
                Ast[nbuf][kc + 3][rr] = pa1.w;
            }
            cp_async_wait0();
            __syncthreads();
        }
    }

    // epilogue: unpack row pairs, float4 per row into partial buffer
    float* p = g_part[ksplit] + (size_t)(rowbase + w * 8) * BN + lane * 4;
    #pragma unroll
    for (int rp = 0; rp < 4; ++rp) {
        float2 c0 = unpk2(acc[rp][0]);
        float2 c1 = unpk2(acc[rp][1]);
        float2 c2 = unpk2(acc[rp][2]);
        float2 c3 = unpk2(acc[rp][3]);
        *(float4*)(p + (size_t)(2 * rp) * BN)     = make_float4(c0.x, c1.x, c2.x, c3.x);
        *(float4*)(p + (size_t)(2 * rp + 1) * BN) = make_float4(c0.y, c1.y, c2.y, c3.y);
    }
}

// ---------------------------------------------------------------------------
// Reduce: out = p0 + p1 + p2 + p3; also resets PDL counters for next replay.
// ---------------------------------------------------------------------------
__global__ void __launch_bounds__(256) reduce_kernel(float* __restrict__ out) {
    if (blockIdx.x == 0 && threadIdx.x < YY + 1) {
        if (threadIdx.x < YY) g_ycnt[threadIdx.x] = 0;
        else                  g_wdone = 0;
    }
    const int idx = blockIdx.x * 256 + threadIdx.x;   // float4 index
    const float4* p0 = (const float4*)g_part[0];
    const float4* p1 = (const float4*)g_part[1];
    const float4* p2 = (const float4*)g_part[2];
    const float4* p3 = (const float4*)g_part[3];
    float4 a = p0[idx], b = p1[idx], c = p2[idx], d = p3[idx];
    float4 r;
    r.x = (a.x + b.x) + (c.x + d.x);
    r.y = (a.y + b.y) + (c.y + d.y);
    r.z = (a.z + b.z) + (c.z + d.z);
    r.w = (a.w + b.w) + (c.w + d.w);
    ((float4*)out)[idx] = r;
}

// ---------------------------------------------------------------------------
// kernel_launch: [weff+gather] -> (PDL-overlapped) K-split GEMM -> reduce
// ---------------------------------------------------------------------------
extern "C" void kernel_launch(void* const* d_in, const int* in_sizes, int n_in,
                              void* d_out, int out_size) {
    const float* emb   = (const float*)d_in[0];
    const float* Wrel  = (const float*)d_in[1];
    const float* Wcite = (const float*)d_in[2];
    const void*  nbr   = d_in[3];
    const void*  cnt   = d_in[4];
    float* out = (float*)d_out;

    gather_mean_kernel<<<NWEFF_BLK + YY * RR * BB, 128>>>(emb, nbr, cnt, Wrel, Wcite);

    // GEMM with programmatic stream serialization (starts under gather tail)
    {
        cudaLaunchConfig_t cfg = {};
        cfg.gridDim  = dim3((MTOT / BM) * NSPLIT, 1, 1);
        cfg.blockDim = dim3(128, 1, 1);
        cudaLaunchAttribute attr[1];
        attr[0].id = cudaLaunchAttributeProgrammaticStreamSerialization;
        attr[0].val.programmaticStreamSerializationAllowed = 1;
        cfg.attrs = attr;
        cfg.numAttrs = 1;
        if (cudaLaunchKernelEx(&cfg, gemm_partial_kernel) != cudaSuccess) {
            gemm_partial_kernel<<<(MTOT / BM) * NSPLIT, 128>>>();
        }
    }

    reduce_kernel<<<(MTOT * II) / (256 * 4), 256>>>(out);
}

// round 15
// speedup vs baseline: 1.0654x; 1.0654x over previous
#include <cuda_runtime.h>

// Problem constants
#define YY 5
#define NN 200000
#define GG 128
#define II 128
#define RR 3
#define BB 1024
#define KK 64
#define KTOT (RR * GG)   // 384

#define NWEFF_BLK 192    // weff-builder CTAs prepended to gather grid
#define NSPLIT 4         // GEMM K-split factor
#define MTOT (YY * BB)   // 5120

// Scratch (no cudaMalloc allowed)
__device__ __align__(16) float g_mean[(size_t)MTOT * KTOT];   // [m][k]
__device__ __align__(16) float g_weff[KTOT * II];             // [k][i]

// ---------------------------------------------------------------------------
// Fused kernel #1 (1D grid, 128 threads)  — EXACT R8 gather (41.1us measured):
//   blocks [0, 192):         build g_weff + zero the output (for RED.ADD)
//   blocks [192, 192+15360): gather + masked mean, one CTA per (y, r, b)
// ---------------------------------------------------------------------------
__global__ void __launch_bounds__(128) gather_mean_kernel(
        const float* __restrict__ emb,
        const void* __restrict__ nbr,
        const void* __restrict__ cnt,
        const float* __restrict__ Wrel,
        const float* __restrict__ Wcite,
        float* __restrict__ out) {
    const int bid = blockIdx.x;
    const int tid = threadIdx.x;

    if (bid < NWEFF_BLK) {
        #pragma unroll
        for (int j = 0; j < 2; ++j) {
            int idx = bid * 256 + j * 128 + tid;   // < 49152
            int r  = idx / (GG * II);
            int gi = idx - r * (GG * II);
            float v;
            if (r == 0)
                v = Wcite[gi] + Wcite[GG * II + gi] + Wcite[2 * GG * II + gi];
            else
                v = Wrel[idx];
            g_weff[idx] = v;
        }
        // zero the output: 655360 floats = 163840 float4, 192 CTAs x 128 thr
        const int nf4 = (MTOT * II) / 4;            // 163840
        float4 z = make_float4(0.f, 0.f, 0.f, 0.f);
        for (int i = bid * 128 + tid; i < nf4; i += NWEFF_BLK * 128)
            ((float4*)out)[i] = z;
        return;
    }

    const int gid = bid - NWEFF_BLK;
    const int y   = gid / (RR * BB);
    const int rem = gid - y * (RR * BB);
    const int r   = rem >> 10;
    const int b   = rem & (BB - 1);
    const int w    = tid >> 5;
    const int lane = tid & 31;

    __shared__ int   s_is64;
    __shared__ int   s_cnt;
    __shared__ __align__(16) int   sidx[KK];
    __shared__ __align__(16) float part[4][GG];

    // dtype detection (warp 0): odd words of first 32 int64 candidates
    if (w == 0) {
        unsigned int v = ((const unsigned int*)cnt)[2 * lane + 1];
        unsigned int m = __ballot_sync(0xffffffffu, v != 0u);
        if (lane == 0) s_is64 = (m == 0u) ? 1 : 0;
    }
    __syncthreads();
    const int is64 = s_is64;

    const long long lin = ((long long)y * RR + r) * BB + b;
    if (tid == 0) {
        s_cnt = is64 ? (int)((const long long*)cnt)[lin]
                     : ((const int*)cnt)[lin];
    }
    if (tid < KK) {
        sidx[tid] = is64 ? (int)((const long long*)nbr)[lin * KK + tid]
                         : ((const int*)nbr)[lin * KK + tid];
    }
    __syncthreads();
    const int count = s_cnt;

    // float4 view of this year's embedding slab; row stride = 32 float4s
    const float4* e = (const float4*)(emb + (size_t)y * NN * GG) + lane;

    float4 acc = make_float4(0.f, 0.f, 0.f, 0.f);
    int k = w;
    for (; k + 4 < count; k += 8) {
        float4 v0 = e[(size_t)sidx[k] * 32];
        float4 v1 = e[(size_t)sidx[k + 4] * 32];
        acc.x += v0.x + v1.x;
        acc.y += v0.y + v1.y;
        acc.z += v0.z + v1.z;
        acc.w += v0.w + v1.w;
    }
    if (k < count) {
        float4 v0 = e[(size_t)sidx[k] * 32];
        acc.x += v0.x; acc.y += v0.y; acc.z += v0.z; acc.w += v0.w;
    }

    *(float4*)&part[w][lane * 4] = acc;
    __syncthreads();

    const float inv = 1.0f / (float)(count > 0 ? count : 1);
    float s = part[0][tid] + part[1][tid] + part[2][tid] + part[3][tid];
    g_mean[((size_t)y * BB + b) * KTOT + r * GG + tid] = s * inv;
}

// ---------------------------------------------------------------------------
// K-split SGEMM (EXACT R8 mainloop) with RED.ADD epilogue straight into out:
//   out[tile] += A[:, s*96:(s+1)*96] @ W[s*96:(s+1)*96, :]   (atomic float add)
// Tile BM=32 x BN=128, BK=32, 3 chunks; 128 threads; grid = 160 x 4 = 640.
// Warp w: rows w*8..w*8+7; lane: cols lane*4..+3 -> 16 f32x2 accs/thread.
// ---------------------------------------------------------------------------
#define BM 32
#define BN 128
#define BK 32
#define KSPL (KTOT / NSPLIT)    // 96
#define NCHUNK (KSPL / BK)      // 3
#define APAD 8

__device__ __forceinline__ unsigned long long fma2(unsigned long long a,
                                                   unsigned long long b,
                                                   unsigned long long c) {
    unsigned long long d;
    asm("fma.rn.f32x2 %0, %1, %2, %3;" : "=l"(d) : "l"(a), "l"(b), "l"(c));
    return d;
}
__device__ __forceinline__ unsigned long long dup2(float x) {
    unsigned long long d;
    unsigned int u = __float_as_uint(x);
    asm("mov.b64 %0, {%1, %1};" : "=l"(d) : "r"(u));
    return d;
}
__device__ __forceinline__ float2 unpk2(unsigned long long p) {
    unsigned int lo, hi;
    asm("mov.b64 {%0, %1}, %2;" : "=r"(lo), "=r"(hi) : "l"(p));
    return make_float2(__uint_as_float(lo), __uint_as_float(hi));
}
__device__ __forceinline__ void cp_async16(unsigned int smem_addr,
                                           const void* gptr) {
    asm volatile("cp.async.ca.shared.global [%0], [%1], 16;\n"
                 :: "r"(smem_addr), "l"(gptr));
}
__device__ __forceinline__ void cp_async_commit() {
    asm volatile("cp.async.commit_group;\n");
}
__device__ __forceinline__ void cp_async_wait0() {
    asm volatile("cp.async.wait_group 0;\n");
}

__global__ void __launch_bounds__(128) gemm_partial_kernel(float* __restrict__ out) {
    __shared__ __align__(16) float Ast[2][BK][BM + APAD];  // transposed A
    __shared__ __align__(16) float Ws[2][BK][BN];

    const int tid  = threadIdx.x;        // 0..127
    const int w    = tid >> 5;           // warp 0..3 -> rows w*8..w*8+7
    const int lane = tid & 31;           // cols lane*4..lane*4+3
    const int ksplit  = blockIdx.x & (NSPLIT - 1);
    const int rowbase = (blockIdx.x >> 2) * BM;
    const int kbase   = ksplit * KSPL;

    unsigned long long acc[4][4];        // [rowpair][col]
    #pragma unroll
    for (int i = 0; i < 4; ++i)
        #pragma unroll
        for (int j = 0; j < 4; ++j) acc[i][j] = 0ull;

    const float* Ag = g_mean + (size_t)rowbase * KTOT + kbase;
    const float* Wg = g_weff + (size_t)kbase * BN;

    const int wrow = tid >> 5;           // 0..3   (k within chunk, +4 per j)
    const int wcol = (tid & 31) << 2;    // 0..124

    unsigned int ws_base[2];
    ws_base[0] = (unsigned int)__cvta_generic_to_shared(&Ws[0][0][0]);
    ws_base[1] = (unsigned int)__cvta_generic_to_shared(&Ws[1][0][0]);

    // prologue: stage chunk 0 (A: 2 float4/thread; W: 8 cp.async/thread)
    {
        #pragma unroll
        for (int j = 0; j < 2; ++j) {
            int l = tid + j * 128;
            int rr = l >> 3, kc = (l & 7) << 2;
            float4 pa = *(const float4*)(Ag + (size_t)rr * KTOT + kc);
            Ast[0][kc + 0][rr] = pa.x;
            Ast[0][kc + 1][rr] = pa.y;
            Ast[0][kc + 2][rr] = pa.z;
            Ast[0][kc + 3][rr] = pa.w;
        }
        #pragma unroll
        for (int j = 0; j < 8; ++j) {
            int kr = wrow + j * 4;       // 0..31
            cp_async16(ws_base[0] + (unsigned int)((kr * BN + wcol) * 4),
                       Wg + (size_t)kr * BN + wcol);
        }
        cp_async_commit();
        cp_async_wait0();
    }
    __syncthreads();

    for (int c = 0; c < NCHUNK; ++c) {
        const int buf = c & 1;
        const bool more = (c + 1 < NCHUNK);
        float4 pa0, pa1;
        if (more) {
            const int k0 = (c + 1) * BK;
            {
                int l = tid;
                pa0 = *(const float4*)(Ag + (size_t)(l >> 3) * KTOT + k0 + ((l & 7) << 2));
                l = tid + 128;
                pa1 = *(const float4*)(Ag + (size_t)(l >> 3) * KTOT + k0 + ((l & 7) << 2));
            }
            #pragma unroll
            for (int j = 0; j < 8; ++j) {
                int kr = wrow + j * 4;
                cp_async16(ws_base[buf ^ 1] + (unsigned int)((kr * BN + wcol) * 4),
                           Wg + (size_t)(k0 + kr) * BN + wcol);
            }
            cp_async_commit();
        }

        #pragma unroll
        for (int kk = 0; kk < BK; ++kk) {
            ulonglong2 aP0 = *(const ulonglong2*)&Ast[buf][kk][w * 8];      // rows 0-3
            ulonglong2 aP1 = *(const ulonglong2*)&Ast[buf][kk][w * 8 + 4];  // rows 4-7
            float4 w4 = *(const float4*)&Ws[buf][kk][lane * 4];
            unsigned long long wd0 = dup2(w4.x), wd1 = dup2(w4.y);
            unsigned long long wd2 = dup2(w4.z), wd3 = dup2(w4.w);

            acc[0][0] = fma2(aP0.x, wd0, acc[0][0]);
            acc[0][1] = fma2(aP0.x, wd1, acc[0][1]);
            acc[0][2] = fma2(aP0.x, wd2, acc[0][2]);
            acc[0][3] = fma2(aP0.x, wd3, acc[0][3]);
            acc[1][0] = fma2(aP0.y, wd0, acc[1][0]);
            acc[1][1] = fma2(aP0.y, wd1, acc[1][1]);
            acc[1][2] = fma2(aP0.y, wd2, acc[1][2]);
            acc[1][3] = fma2(aP0.y, wd3, acc[1][3]);
            acc[2][0] = fma2(aP1.x, wd0, acc[2][0]);
            acc[2][1] = fma2(aP1.x, wd1, acc[2][1]);
            acc[2][2] = fma2(aP1.x, wd2, acc[2][2]);
            acc[2][3] = fma2(aP1.x, wd3, acc[2][3]);
            acc[3][0] = fma2(aP1.y, wd0, acc[3][0]);
            acc[3][1] = fma2(aP1.y, wd1, acc[3][1]);
            acc[3][2] = fma2(aP1.y, wd2, acc[3][2]);
            acc[3][3] = fma2(aP1.y, wd3, acc[3][3]);
        }

        if (more) {
            const int nbuf = buf ^ 1;
            {
                int l = tid;
                int rr = l >> 3, kc = (l & 7) << 2;
                Ast[nbuf][kc + 0][rr] = pa0.x;
                Ast[nbuf][kc + 1][rr] = pa0.y;
                Ast[nbuf][kc + 2][rr] = pa0.z;
                Ast[nbuf][kc + 3][rr] = pa0.w;
                l = tid + 128;
                rr = l >> 3; kc = (l & 7) << 2;
                Ast[nbuf][kc + 0][rr] = pa1.x;
                Ast[nbuf][kc + 1][rr] = pa1.y;
                Ast[nbuf][kc + 2][rr] = pa1.z;
                Ast[nbuf][kc + 3][rr] = pa1.w;
            }
            cp_async_wait0();
            __syncthreads();
        }
    }

    // epilogue: unpack row pairs, RED.ADD into out (out zeroed by kernel 1)
    float* o = out + (size_t)(rowbase + w * 8) * BN + lane * 4;
    #pragma unroll
    for (int rp = 0; rp < 4; ++rp) {
        float2 c0 = unpk2(acc[rp][0]);
        float2 c1 = unpk2(acc[rp][1]);
        float2 c2 = unpk2(acc[rp][2]);
        float2 c3 = unpk2(acc[rp][3]);
        float* r0 = o + (size_t)(2 * rp) * BN;
        float* r1 = o + (size_t)(2 * rp + 1) * BN;
        atomicAdd(r0 + 0, c0.x);
        atomicAdd(r0 + 1, c1.x);
        atomicAdd(r0 + 2, c2.x);
        atomicAdd(r0 + 3, c3.x);
        atomicAdd(r1 + 0, c0.y);
        atomicAdd(r1 + 1, c1.y);
        atomicAdd(r1 + 2, c2.y);
        atomicAdd(r1 + 3, c3.y);
    }
}

// ---------------------------------------------------------------------------
// kernel_launch: [weff-build + out-zero + gather] -> K-split GEMM (RED.ADD)
// ---------------------------------------------------------------------------
extern "C" void kernel_launch(void* const* d_in, const int* in_sizes, int n_in,
                              void* d_out, int out_size) {
    const float* emb   = (const float*)d_in[0];
    const float* Wrel  = (const float*)d_in[1];
    const float* Wcite = (const float*)d_in[2];
    const void*  nbr   = d_in[3];
    const void*  cnt   = d_in[4];
    float* out = (float*)d_out;

    gather_mean_kernel<<<NWEFF_BLK + YY * RR * BB, 128>>>(emb, nbr, cnt, Wrel, Wcite, out);

    gemm_partial_kernel<<<(MTOT / BM) * NSPLIT, 128>>>(out);
}